// round 12
// baseline (speedup 1.0000x reference)
#include <cuda_runtime.h>

typedef unsigned long long u64;

#define NB   4
#define NTOK 4096
#define DIM  256
#define BM   64
#define BN   64

// scratch for projected_val = val @ Wv  (16 MB, static device array — no allocs)
__device__ float g_pv[NB * NTOK * DIM];

__device__ __forceinline__ u64 ffma2(u64 a, u64 b, u64 c) {
    u64 d;
    asm("fma.rn.f32x2 %0, %1, %2, %3;" : "=l"(d) : "l"(a), "l"(b), "l"(c));
    return d;
}
__device__ __forceinline__ u64 pack2(float lo, float hi) {
    u64 r;
    asm("mov.b64 %0, {%1, %2};" : "=l"(r) : "f"(lo), "f"(hi));
    return r;
}
__device__ __forceinline__ float2 unpack2(u64 v) {
    float2 f;
    asm("mov.b64 {%0, %1}, %2;" : "=f"(f.x), "=f"(f.y) : "l"(v));
    return f;
}

// ---------------------------------------------------------------------------
// Kernel A: PV[b,m,:] = val[b,m,:] @ Wv   (M=16384, N=256, K=256)
// 64-row tiles, f32x2 packed over output-column pairs.
// ---------------------------------------------------------------------------
__global__ void __launch_bounds__(256) pv_gemm_kernel(const float* __restrict__ val,
                                                      const float* __restrict__ Wv) {
    __shared__ float sA[64][33];    // [row][k]  pad 33 -> conflict-free
    __shared__ u64   sW[32][128];   // [k][e-pair]
    const int tid = threadIdx.x;
    const int tx = tid & 15;
    const int ty = tid >> 4;
    const int row0 = blockIdx.x * 64;

    u64 acc[4][8];
#pragma unroll
    for (int r = 0; r < 4; r++)
#pragma unroll
        for (int c = 0; c < 8; c++) acc[r][c] = 0ull;

    for (int kt = 0; kt < DIM; kt += 32) {
        __syncthreads();
#pragma unroll
        for (int t = tid; t < 64 * 32; t += 256) {
            int i = t >> 5, k = t & 31;
            sA[i][k] = val[(size_t)(row0 + i) * DIM + kt + k];
        }
#pragma unroll
        for (int t = tid; t < 32 * 128; t += 256) {
            int k = t >> 7, e2 = t & 127;
            sW[k][e2] = ((const u64*)(Wv + (size_t)(kt + k) * DIM))[e2];
        }
        __syncthreads();
#pragma unroll
        for (int k = 0; k < 32; k++) {
            u64 b2[8];
#pragma unroll
            for (int c = 0; c < 8; c++) b2[c] = sW[k][tx + 16 * c];
#pragma unroll
            for (int r = 0; r < 4; r++) {
                float a = sA[ty * 4 + r][k];
                u64 a2 = pack2(a, a);
#pragma unroll
                for (int c = 0; c < 8; c++) acc[r][c] = ffma2(a2, b2[c], acc[r][c]);
            }
        }
    }
#pragma unroll
    for (int r = 0; r < 4; r++) {
        u64* orow = (u64*)(g_pv + (size_t)(row0 + ty * 4 + r) * DIM);
#pragma unroll
        for (int c = 0; c < 8; c++) orow[tx + 16 * c] = acc[r][c];
    }
}

// ---------------------------------------------------------------------------
// Kernel B: fused propagation.
// Per CTA: one 64-row n-tile of one batch. Loop over 64 m-tiles:
//   phase 1: S = Vn . Vm^T (f32x2 over d-pairs), softsign -> E
//            delta_state partials accumulated from registers
//            E written transposed to smem
//   phase 2: acc[64x256] += E @ PV_m  (f32x2 over e-pairs)
// Shared layouts (u64 elements, conflict-free by construction):
//   sVn,sVm : [d2][i] stride 65  (writes: bank step 2; reads: lanes step 1)
//   sPV     : [j][e2] stride 128 (lanes step 1 in tx)
//   sET     : float [j][i] stride 68 (16B-aligned rows for LDS.128)
// ---------------------------------------------------------------------------
extern __shared__ __align__(16) unsigned char smem_raw[];

__global__ void __launch_bounds__(256, 1) prop_kernel(const float* __restrict__ val,
                                                      const float* __restrict__ state,
                                                      float* __restrict__ out_state,
                                                      float* __restrict__ out_val) {
    u64*   sVn    = (u64*)smem_raw;          // 128*65 u64
    u64*   sVm    = sVn + 128 * 65;          // 128*65 u64
    u64*   sPV    = sVm + 128 * 65;          // 64*128 u64
    float* sET    = (float*)(sPV + 64 * 128); // 64*68 f32
    float* sState = sET + 64 * 68;            // 64 f32

    const int tid = threadIdx.x;
    const int tx = tid & 15;
    const int ty = tid >> 4;
    const int b  = blockIdx.y;
    const int n0 = blockIdx.x * BM;

    const float* valb   = val  + (size_t)b * NTOK * DIM;
    const float* pvb    = g_pv + (size_t)b * NTOK * DIM;
    const float* stateb = state + (size_t)b * NTOK;

    // load Vn once: transposed-packed [d2][i]
#pragma unroll
    for (int t = tid; t < 64 * 128; t += 256) {
        int i = t >> 7, d2 = t & 127;
        sVn[d2 * 65 + i] = ((const u64*)(valb + (size_t)(n0 + i) * DIM))[d2];
    }

    u64 acc[4][8];
#pragma unroll
    for (int r = 0; r < 4; r++)
#pragma unroll
        for (int c = 0; c < 8; c++) acc[r][c] = 0ull;
    float ds[4] = {0.f, 0.f, 0.f, 0.f};

    for (int mt = 0; mt < NTOK / BN; mt++) {
        const int m0 = mt * BN;
        __syncthreads();  // previous phase-2 readers done before overwriting tiles
#pragma unroll
        for (int t = tid; t < 64 * 128; t += 256) {
            int j = t >> 7, d2 = t & 127;
            sVm[d2 * 65 + j] = ((const u64*)(valb + (size_t)(m0 + j) * DIM))[d2];
        }
#pragma unroll
        for (int t = tid; t < 64 * 128; t += 256) {
            int j = t >> 7, e2 = t & 127;
            sPV[j * 128 + e2] = ((const u64*)(pvb + (size_t)(m0 + j) * DIM))[e2];
        }
        if (tid < 64) sState[tid] = stateb[m0 + tid];
        __syncthreads();

        // ---- phase 1: S tile + softsign + state aggregation ----
        u64 S2[4][4];
#pragma unroll
        for (int r = 0; r < 4; r++)
#pragma unroll
            for (int c = 0; c < 4; c++) S2[r][c] = 0ull;

#pragma unroll 4
        for (int d2 = 0; d2 < 128; d2++) {
            u64 a2[4], b2[4];
#pragma unroll
            for (int r = 0; r < 4; r++) a2[r] = sVn[d2 * 65 + ty * 4 + r];
#pragma unroll
            for (int c = 0; c < 4; c++) b2[c] = sVm[d2 * 65 + tx + 16 * c];
#pragma unroll
            for (int r = 0; r < 4; r++)
#pragma unroll
                for (int c = 0; c < 4; c++) S2[r][c] = ffma2(a2[r], b2[c], S2[r][c]);
        }

#pragma unroll
        for (int r = 0; r < 4; r++) {
#pragma unroll
            for (int c = 0; c < 4; c++) {
                float2 p = unpack2(S2[r][c]);
                float s = p.x + p.y;                       // i = ty*4+r, j = tx+16c
                float e = __fdividef(s, 1.0f + fabsf(s));  // softsign
                ds[r] += e * sState[tx + 16 * c];
                sET[(tx + 16 * c) * 68 + ty * 4 + r] = e;  // E transposed [j][i]
            }
        }
        __syncthreads();

        // ---- phase 2: acc += E @ PV_m ----
#pragma unroll 2
        for (int j = 0; j < 64; j++) {
            float4 ev = *(const float4*)(sET + j * 68 + ty * 4);
            u64 b2[8];
#pragma unroll
            for (int c = 0; c < 8; c++) b2[c] = sPV[j * 128 + tx + 16 * c];
            u64 a0 = pack2(ev.x, ev.x);
            u64 a1 = pack2(ev.y, ev.y);
            u64 a2 = pack2(ev.z, ev.z);
            u64 a3 = pack2(ev.w, ev.w);
#pragma unroll
            for (int c = 0; c < 8; c++) {
                acc[0][c] = ffma2(a0, b2[c], acc[0][c]);
                acc[1][c] = ffma2(a1, b2[c], acc[1][c]);
                acc[2][c] = ffma2(a2, b2[c], acc[2][c]);
                acc[3][c] = ffma2(a3, b2[c], acc[3][c]);
            }
        }
    }

    // ---- epilogue: reduce delta_state over the 16 tx lanes (within warp) ----
#pragma unroll
    for (int r = 0; r < 4; r++) {
        float v = ds[r];
        v += __shfl_xor_sync(0xffffffffu, v, 8);
        v += __shfl_xor_sync(0xffffffffu, v, 4);
        v += __shfl_xor_sync(0xffffffffu, v, 2);
        v += __shfl_xor_sync(0xffffffffu, v, 1);
        ds[r] = v;
    }
    if (tx == 0) {
#pragma unroll
        for (int r = 0; r < 4; r++)
            out_state[(size_t)b * NTOK + n0 + ty * 4 + r] = ds[r];
    }

    // ---- delta_val store (coalesced 8B) ----
#pragma unroll
    for (int r = 0; r < 4; r++) {
        u64* orow = (u64*)(out_val + ((size_t)b * NTOK + n0 + ty * 4 + r) * DIM);
#pragma unroll
        for (int c = 0; c < 8; c++) orow[tx + 16 * c] = acc[r][c];
    }
}

// ---------------------------------------------------------------------------
extern "C" void kernel_launch(void* const* d_in, const int* in_sizes, int n_in,
                              void* d_out, int out_size) {
    const float* val   = (const float*)d_in[0];  // [4,4096,256]
    const float* state = (const float*)d_in[1];  // [4,4096]
    const float* Wv    = (const float*)d_in[2];  // [256,256]
    float* out_state = (float*)d_out;                 // [4,4096]
    float* out_val   = (float*)d_out + NB * NTOK;     // [4,4096,256]

    pv_gemm_kernel<<<NB * NTOK / 64, 256>>>(val, Wv);

    const size_t smem = (size_t)(128 * 65 * 2 + 64 * 128) * sizeof(u64)
                      + (size_t)(64 * 68 + 64) * sizeof(float);   // 216,320 B
    cudaFuncSetAttribute(prop_kernel, cudaFuncAttributeMaxDynamicSharedMemorySize,
                         (int)smem);
    dim3 grid(NTOK / BM, NB);
    prop_kernel<<<grid, 256, smem>>>(val, state, out_state, out_val);
}